// round 2
// baseline (speedup 1.0000x reference)
#include <cuda_runtime.h>

#define RWIN 8
constexpr int H = 256, W = 256, PLANES = 12;
constexpr int HH = 1024, WH = 1024;
constexpr float EPSF  = 1e-8f;
constexpr float EPSSF = 1e-12f;
constexpr int PSZ = PLANES * H * W;
constexpr int PITCH = 257;                 // shared pitch, conflict-free

// ---- static device scratch ----
__device__ float g_partial[96];
__device__ float g_hsum[6 * PSZ];
__device__ float g_ab  [2 * PSZ];
__device__ float g_hab [2 * PSZ];
__device__ float g_mab [2 * PSZ];

// ---------- stage 0: partial sums of |l_a|+eps ----------
__global__ void k_reduce1(const float* __restrict__ la) {
    __shared__ float sm[256];
    int t = threadIdx.x;
    int base = blockIdx.x * 8192;
    float s = 0.f;
#pragma unroll
    for (int k = 0; k < 32; k++)
        s += fabsf(la[base + k * 256 + t]) + EPSSF;
    sm[t] = s; __syncthreads();
    for (int off = 128; off > 0; off >>= 1) {
        if (t < off) sm[t] += sm[t + off];
        __syncthreads();
    }
    if (t == 0) g_partial[blockIdx.x] = sm[0];
}

// ---------- stage 1: products + horizontal box (sliding) ----------
// block = 16 rows of one plane; phase1: thread=column; phase2: thread handles
// a 16-col segment of one row with a running window sum.
__global__ void k_hbox(const float* __restrict__ lx,
                       const float* __restrict__ ly,
                       const float* __restrict__ la) {
    extern __shared__ float sp[];          // [6][16][PITCH]
    int t = threadIdx.x;
    int plane = blockIdx.x >> 4, rb = blockIdx.x & 15;
    int row0 = rb * 16;
    int pbase = plane * H * W;

#pragma unroll 4
    for (int r = 0; r < 16; r++) {
        int idx = pbase + (row0 + r) * W + t;
        float a = fabsf(la[idx]) + EPSSF;
        float x = lx[idx], y = ly[idx];
        float ax = a * x;
        sp[(0*16 + r) * PITCH + t] = a;
        sp[(1*16 + r) * PITCH + t] = ax * a * y;
        sp[(2*16 + r) * PITCH + t] = ax * a;
        sp[(3*16 + r) * PITCH + t] = a * y;
        sp[(4*16 + r) * PITCH + t] = ax * ax;
        sp[(5*16 + r) * PITCH + t] = ax;
    }
    __syncthreads();

    int seg = t >> 4, rloc = t & 15;
    int col0 = seg * 16;
    float s[6] = {0,0,0,0,0,0};
    int lo = col0 - RWIN < 0 ? 0 : col0 - RWIN;
    for (int k = lo; k <= col0 + RWIN; k++) {
#pragma unroll
        for (int c = 0; c < 6; c++) s[c] += sp[(c*16 + rloc) * PITCH + k];
    }
    int orow = pbase + (row0 + rloc) * W;
#pragma unroll
    for (int i = 0; i < 16; i++) {
        int col = col0 + i;
        if (i > 0) {
            int add = col + RWIN, sub = col - RWIN - 1;
            if (add < W) {
#pragma unroll
                for (int c = 0; c < 6; c++) s[c] += sp[(c*16 + rloc) * PITCH + add];
            }
            if (sub >= 0) {
#pragma unroll
                for (int c = 0; c < 6; c++) s[c] -= sp[(c*16 + rloc) * PITCH + sub];
            }
        }
#pragma unroll
        for (int c = 0; c < 6; c++) g_hsum[c * PSZ + orow + col] = s[c];
    }
}

// ---------- stage 2: vertical box (sliding) + A,b ----------
__global__ void k_vbox_ab() {
    __shared__ float sm[256];
    __shared__ float s_inv;
    int t = threadIdx.x;
    sm[t] = (t < 96) ? g_partial[t] : 0.f;
    __syncthreads();
    for (int off = 128; off > 0; off >>= 1) {
        if (t < off) sm[t] += sm[t + off];
        __syncthreads();
    }
    if (t == 0) s_inv = 1.0f / sm[0];
    __syncthreads();
    float invS = s_inv;

    int plane = blockIdx.x >> 4, sb = blockIdx.x & 15;
    int row0 = sb * 16;
    int pbase = plane * H * W;

    float s[6] = {0,0,0,0,0,0};
    int lo = row0 - RWIN < 0 ? 0 : row0 - RWIN;
    for (int r = lo; r <= row0 + RWIN; r++) {
        int idx = pbase + r * W + t;
#pragma unroll
        for (int c = 0; c < 6; c++) s[c] += g_hsum[c * PSZ + idx];
    }
    int nx = min(W - 1, t + RWIN) - max(0, t - RWIN) + 1;

    for (int i = 0; i < 16; i++) {
        int row = row0 + i;
        if (i > 0) {
            int add = row + RWIN, sub = row - RWIN - 1;
            if (add < H) {
                int idx = pbase + add * W + t;
#pragma unroll
                for (int c = 0; c < 6; c++) s[c] += g_hsum[c * PSZ + idx];
            }
            if (sub >= 0) {
                int idx = pbase + sub * W + t;
#pragma unroll
                for (int c = 0; c < 6; c++) s[c] -= g_hsum[c * PSZ + idx];
            }
        }
        int ny = min(H - 1, row + RWIN) - max(0, row - RWIN) + 1;
        float Nf = (float)(nx * ny);
        float invN = 1.0f / Nf;

        float m_a    = s[0] * invN;
        float m_a2xy = s[1] * invN;
        float m_tax  = invS * s[2] * invN;
        float m_ay   = s[3] * invN;
        float m_a2x2 = s[4] * invN;
        float m_ax   = s[5] * invN;

        float temp = fabsf(m_a2x2 - Nf * m_tax * m_ax);
        float A = (m_a2xy - Nf * m_tax * m_ay) / (temp + EPSF);
        float b = (m_ay - A * m_ax) / m_a;

        int o = pbase + row * W + t;
        g_ab[o]       = A;
        g_ab[PSZ + o] = b;
    }
}

// ---------- stage 3: horizontal box of A,b (sliding) ----------
__global__ void k_hbox2() {
    __shared__ float sp[2 * 16 * PITCH];
    int t = threadIdx.x;
    int plane = blockIdx.x >> 4, rb = blockIdx.x & 15;
    int row0 = rb * 16;
    int pbase = plane * H * W;

#pragma unroll 4
    for (int r = 0; r < 16; r++) {
        int idx = pbase + (row0 + r) * W + t;
        sp[(0*16 + r) * PITCH + t] = g_ab[idx];
        sp[(1*16 + r) * PITCH + t] = g_ab[PSZ + idx];
    }
    __syncthreads();

    int seg = t >> 4, rloc = t & 15;
    int col0 = seg * 16;
    float sa = 0.f, sb = 0.f;
    int lo = col0 - RWIN < 0 ? 0 : col0 - RWIN;
    for (int k = lo; k <= col0 + RWIN; k++) {
        sa += sp[(0*16 + rloc) * PITCH + k];
        sb += sp[(1*16 + rloc) * PITCH + k];
    }
    int orow = pbase + (row0 + rloc) * W;
#pragma unroll
    for (int i = 0; i < 16; i++) {
        int col = col0 + i;
        if (i > 0) {
            int add = col + RWIN, sub = col - RWIN - 1;
            if (add < W) { sa += sp[(0*16 + rloc) * PITCH + add];
                           sb += sp[(1*16 + rloc) * PITCH + add]; }
            if (sub >= 0){ sa -= sp[(0*16 + rloc) * PITCH + sub];
                           sb -= sp[(1*16 + rloc) * PITCH + sub]; }
        }
        g_hab[orow + col]       = sa;
        g_hab[PSZ + orow + col] = sb;
    }
}

// ---------- stage 4: vertical box of A,b (sliding) -> means ----------
__global__ void k_vbox2() {
    int t = threadIdx.x;
    int plane = blockIdx.x >> 4, sb = blockIdx.x & 15;
    int row0 = sb * 16;
    int pbase = plane * H * W;

    float sa = 0.f, sbv = 0.f;
    int lo = row0 - RWIN < 0 ? 0 : row0 - RWIN;
    for (int r = lo; r <= row0 + RWIN; r++) {
        int idx = pbase + r * W + t;
        sa  += g_hab[idx];
        sbv += g_hab[PSZ + idx];
    }
    int nx = min(W - 1, t + RWIN) - max(0, t - RWIN) + 1;

    for (int i = 0; i < 16; i++) {
        int row = row0 + i;
        if (i > 0) {
            int add = row + RWIN, sub = row - RWIN - 1;
            if (add < H) { int idx = pbase + add * W + t;
                           sa += g_hab[idx]; sbv += g_hab[PSZ + idx]; }
            if (sub >= 0){ int idx = pbase + sub * W + t;
                           sa -= g_hab[idx]; sbv -= g_hab[PSZ + idx]; }
        }
        int ny = min(H - 1, row + RWIN) - max(0, row - RWIN) + 1;
        float invN = 1.0f / (float)(nx * ny);
        int o = pbase + row * W + t;
        g_mab[o]       = sa * invN;
        g_mab[PSZ + o] = sbv * invN;
    }
}

// ---------- stage 5: bilinear 4x upsample fused with hr_x ----------
// block = one output row of one plane; A/B vertically interpolated once into
// shared, then 4 px/thread with float4 global traffic.
__global__ void k_up(const float* __restrict__ hr, float* __restrict__ out) {
    __shared__ float sA[256], sB[256];
    int t = threadIdx.x;
    int Y = blockIdx.y, plane = blockIdx.z;
    const float sc = 255.0f / 1023.0f;

    float yf = Y * sc;
    int y0 = (int)yf;
    int y1 = min(y0 + 1, H - 1);
    float wy = yf - (float)y0;

    int pb = plane * H * W;
    float a0 = g_mab[pb + y0 * W + t], a1 = g_mab[pb + y1 * W + t];
    float b0 = g_mab[PSZ + pb + y0 * W + t], b1 = g_mab[PSZ + pb + y1 * W + t];
    sA[t] = a0 * (1.f - wy) + a1 * wy;
    sB[t] = b0 * (1.f - wy) + b1 * wy;
    __syncthreads();

    int X = t * 4;
    int ho = plane * HH * WH + Y * WH + X;
    float4 h = *(const float4*)(hr + ho);
    float4 o;
    float* hv = (float*)&h;
    float* ov = (float*)&o;
#pragma unroll
    for (int k = 0; k < 4; k++) {
        float xf = (X + k) * sc;
        int x0 = (int)xf;
        int x1 = min(x0 + 1, W - 1);
        float wx = xf - (float)x0;
        float Av = sA[x0] * (1.f - wx) + sA[x1] * wx;
        float Bv = sB[x0] * (1.f - wx) + sB[x1] * wx;
        ov[k] = Av * hv[k] + Bv;
    }
    *(float4*)(out + ho) = o;
}

extern "C" void kernel_launch(void* const* d_in, const int* in_sizes, int n_in,
                              void* d_out, int out_size) {
    const float* lr_x = (const float*)d_in[0];
    const float* lr_y = (const float*)d_in[1];
    const float* hr_x = (const float*)d_in[2];
    const float* l_a  = (const float*)d_in[3];
    float* out = (float*)d_out;

    static const int HBOX_SMEM = 6 * 16 * PITCH * 4;   // 98688 B
    cudaFuncSetAttribute(k_hbox, cudaFuncAttributeMaxDynamicSharedMemorySize,
                         HBOX_SMEM);

    k_reduce1<<<96, 256>>>(l_a);
    k_hbox<<<PLANES * 16, 256, HBOX_SMEM>>>(lr_x, lr_y, l_a);
    k_vbox_ab<<<PLANES * 16, 256>>>();
    k_hbox2<<<PLANES * 16, 256>>>();
    k_vbox2<<<PLANES * 16, 256>>>();
    dim3 g(1, HH, PLANES);
    k_up<<<g, 256>>>(hr_x, out);
}

// round 3
// speedup vs baseline: 1.0181x; 1.0181x over previous
#include <cuda_runtime.h>

#define RWIN 8
constexpr int H = 256, W = 256, PLANES = 12;
constexpr int HH = 1024, WH = 1024;
constexpr float EPSF  = 1e-8f;
constexpr float EPSSF = 1e-12f;
constexpr int PSZ = PLANES * H * W;

constexpr int TILE = 32;            // output tile (mean A/b) per block
constexpr int PP = 65;              // products pitch (64 cols + 1)
constexpr int HP = 49;              // hsum / AB pitch (48 cols + 1)
constexpr int BP = 33;              // HAB pitch (32 cols + 1)

// shared layout (floats):
//  prod  [6][64][PP]  @ 0          (24960)
//  hsum  [6][64][HP]  @ 24960      (18816)
//  AB    [2][48][HP]  @ 0   (alias dead prod)   (4704)
//  HAB   [2][48][BP]  @ 4704 (alias dead prod)  (3168)
//  sred  [97]         @ 43776
constexpr int SM_HSUM = 6 * 64 * PP;            // 24960
constexpr int SM_SRED = SM_HSUM + 6 * 64 * HP;  // 43776
constexpr int SM_FLOATS = SM_SRED + 97;         // 43873
constexpr int SMEM_BYTES = SM_FLOATS * 4;       // 175492 B

__device__ float g_partial[96];
__device__ float g_mab[2 * PSZ];

// ---------- stage 0: partial sums of |l_a|+eps ----------
__global__ void k_reduce1(const float* __restrict__ la) {
    __shared__ float sm[256];
    int t = threadIdx.x;
    int base = blockIdx.x * 8192;
    float s = 0.f;
#pragma unroll
    for (int k = 0; k < 32; k++)
        s += fabsf(la[base + k * 256 + t]) + EPSSF;
    sm[t] = s; __syncthreads();
    for (int off = 128; off > 0; off >>= 1) {
        if (t < off) sm[t] += sm[t + off];
        __syncthreads();
    }
    if (t == 0) g_partial[blockIdx.x] = sm[0];
}

// ---------- stage 1: whole low-res pipeline, one kernel ----------
__global__ __launch_bounds__(512, 1)
void k_fused(const float* __restrict__ lx,
             const float* __restrict__ ly,
             const float* __restrict__ la) {
    extern __shared__ float sm[];
    float* prod = sm;                 // 6 x 64 x PP
    float* hsum = sm + SM_HSUM;       // 6 x 64 x HP
    float* AB   = sm;                 // 2 x 48 x HP (alias)
    float* HAB  = sm + 2 * 48 * HP;   // 2 x 48 x BP (alias)
    float* sred = sm + SM_SRED;

    int t = threadIdx.x;
    int b = blockIdx.x;
    int plane = b >> 6;
    int tile  = b & 63;
    int R0 = (tile >> 3) * TILE;
    int C0 = (tile & 7) * TILE;
    int pbase = plane * H * W;

    // --- phase 0: invS (tiny reduce of 96 partials) ---
    if (t < 96) sred[t] = g_partial[t];
    __syncthreads();
    if (t == 0) {
        float s = 0.f;
        for (int i = 0; i < 96; i++) s += sred[i];
        sred[96] = 1.0f / s;
    }

    // --- phase 1: load 64x64 halo + form 6 products ---
    for (int i = t; i < 64 * 64; i += 512) {
        int lr = i >> 6, lc = i & 63;
        int gr = R0 - 16 + lr, gc = C0 - 16 + lc;
        float a = 0.f, x = 0.f, y = 0.f;
        if (gr >= 0 && gr < H && gc >= 0 && gc < W) {
            int idx = pbase + gr * W + gc;
            a = fabsf(la[idx]) + EPSSF;
            x = lx[idx];
            y = ly[idx];
        }
        float ax = a * x;
        int o = lr * PP + lc;
        prod[0 * 64 * PP + o] = a;
        prod[1 * 64 * PP + o] = ax * a * y;
        prod[2 * 64 * PP + o] = ax * a;
        prod[3 * 64 * PP + o] = a * y;
        prod[4 * 64 * PP + o] = ax * ax;
        prod[5 * 64 * PP + o] = ax;
    }
    __syncthreads();

    // --- phase 2: horizontal box (sliding), 6ch x 64 rows = 384 jobs ---
    if (t < 384) {
        int ch = t / 64, lr = t % 64;
        int gr = R0 - 16 + lr;
        if (gr >= 0 && gr < H) {
            const float* p = prod + ch * 64 * PP + lr * PP;
            float* hs = hsum + ch * 64 * HP + lr * HP;
            int cbeg = max(0, C0 - 8), cend = min(W - 1, C0 + 39);
            int lo = max(0, cbeg - 8), hi = min(W - 1, cbeg + 8);
            float s = 0.f;
            for (int g = lo; g <= hi; g++) s += p[g - (C0 - 16)];
            hs[cbeg - (C0 - 8)] = s;
            for (int c = cbeg + 1; c <= cend; c++) {
                int add = c + 8, sub = c - 9;
                if (add <= W - 1) s += p[add - (C0 - 16)];
                if (sub >= 0)     s -= p[sub - (C0 - 16)];
                hs[c - (C0 - 8)] = s;
            }
        }
    }
    __syncthreads();

    // --- phase 3: vertical box + A,b. jobs: 48 cols x 8 row-segs = 384 ---
    float invS = sred[96];
    if (t < 384) {
        int lc = t % 48, seg = t / 48;
        int q = C0 - 8 + lc;                    // global col of A,b
        if (q >= 0 && q < W) {
            int nx = min(W - 1, q + 8) - max(0, q - 8) + 1;
            int arbeg = R0 - 8 + seg * 6;
            int arS = max(arbeg, 0);
            int arE = min(arbeg + 5, H - 1);
            if (arS <= arE) {
                int lo = max(0, arS - 8), hi = min(H - 1, arS + 8);
                float s[6] = {0,0,0,0,0,0};
                for (int g = lo; g <= hi; g++) {
                    int ro = (g - (R0 - 16)) * HP + lc;
#pragma unroll
                    for (int c2 = 0; c2 < 6; c2++) s[c2] += hsum[c2 * 64 * HP + ro];
                }
                for (int ar = arS; ar <= arE; ar++) {
                    if (ar > arS) {
                        int add = ar + 8, sub = ar - 9;
                        if (add <= H - 1) {
                            int ro = (add - (R0 - 16)) * HP + lc;
#pragma unroll
                            for (int c2 = 0; c2 < 6; c2++) s[c2] += hsum[c2 * 64 * HP + ro];
                        }
                        if (sub >= 0) {
                            int ro = (sub - (R0 - 16)) * HP + lc;
#pragma unroll
                            for (int c2 = 0; c2 < 6; c2++) s[c2] -= hsum[c2 * 64 * HP + ro];
                        }
                    }
                    int ny = min(H - 1, ar + 8) - max(0, ar - 8) + 1;
                    float Nf = (float)(nx * ny);
                    float invN = 1.0f / Nf;

                    float m_a    = s[0] * invN;
                    float m_a2xy = s[1] * invN;
                    float m_tax  = invS * s[2] * invN;
                    float m_ay   = s[3] * invN;
                    float m_a2x2 = s[4] * invN;
                    float m_ax   = s[5] * invN;

                    float temp = fabsf(m_a2x2 - Nf * m_tax * m_ax);
                    float A = (m_a2xy - Nf * m_tax * m_ay) / (temp + EPSF);
                    float bb = (m_ay - A * m_ax) / m_a;

                    int o = (ar - (R0 - 8)) * HP + lc;
                    AB[0 * 48 * HP + o] = A;
                    AB[1 * 48 * HP + o] = bb;
                }
            }
        }
    }
    __syncthreads();

    // --- phase 4: horizontal box of A,b. jobs: 2ch x 48 rows = 96 ---
    if (t < 96) {
        int ch = t / 48, lrow = t % 48;
        int ar = R0 - 8 + lrow;
        if (ar >= 0 && ar < H) {
            const float* src = AB + ch * 48 * HP + lrow * HP;
            float* dst = HAB + ch * 48 * BP + lrow * BP;
            int lo = max(0, C0 - 8), hi = min(W - 1, C0 + 8);
            float s = 0.f;
            for (int g = lo; g <= hi; g++) s += src[g - (C0 - 8)];
            dst[0] = s;
            for (int k = 1; k < 32; k++) {
                int c = C0 + k;
                int add = c + 8, sub = c - 9;
                if (add <= W - 1) s += src[add - (C0 - 8)];
                if (sub >= 0)     s -= src[sub - (C0 - 8)];
                dst[k] = s;
            }
        }
    }
    __syncthreads();

    // --- phase 5: vertical box of A,b -> g_mab. jobs: 2ch x 32 cols = 64 ---
    if (t < 64) {
        int ch = t >> 5, lc = t & 31;
        int oc = C0 + lc;
        int nx2 = min(W - 1, oc + 8) - max(0, oc - 8) + 1;
        const float* src = HAB + ch * 48 * BP;
        int lo = max(0, R0 - 8), hi = min(H - 1, R0 + 8);
        float s = 0.f;
        for (int g = lo; g <= hi; g++) s += src[(g - (R0 - 8)) * BP + lc];
        float* dst = g_mab + ch * PSZ + pbase;
        for (int k = 0; k < 32; k++) {
            int r = R0 + k;
            if (k > 0) {
                int add = r + 8, sub = r - 9;
                if (add <= H - 1) s += src[(add - (R0 - 8)) * BP + lc];
                if (sub >= 0)     s -= src[(sub - (R0 - 8)) * BP + lc];
            }
            int ny2 = min(H - 1, r + 8) - max(0, r - 8) + 1;
            dst[r * W + oc] = s / (float)(nx2 * ny2);
        }
    }
}

// ---------- stage 2: bilinear 4x upsample fused with hr_x ----------
__global__ void k_up(const float* __restrict__ hr, float* __restrict__ out) {
    __shared__ float sA[256], sB[256];
    int t = threadIdx.x;
    int Y = blockIdx.y, plane = blockIdx.z;
    const float sc = 255.0f / 1023.0f;

    float yf = Y * sc;
    int y0 = (int)yf;
    int y1 = min(y0 + 1, H - 1);
    float wy = yf - (float)y0;

    int pb = plane * H * W;
    float a0 = g_mab[pb + y0 * W + t], a1 = g_mab[pb + y1 * W + t];
    float b0 = g_mab[PSZ + pb + y0 * W + t], b1 = g_mab[PSZ + pb + y1 * W + t];
    sA[t] = a0 * (1.f - wy) + a1 * wy;
    sB[t] = b0 * (1.f - wy) + b1 * wy;
    __syncthreads();

    int X = t * 4;
    int ho = plane * HH * WH + Y * WH + X;
    float4 h = *(const float4*)(hr + ho);
    float4 o;
    float* hv = (float*)&h;
    float* ov = (float*)&o;
#pragma unroll
    for (int k = 0; k < 4; k++) {
        float xf = (X + k) * sc;
        int x0 = (int)xf;
        int x1 = min(x0 + 1, W - 1);
        float wx = xf - (float)x0;
        float Av = sA[x0] * (1.f - wx) + sA[x1] * wx;
        float Bv = sB[x0] * (1.f - wx) + sB[x1] * wx;
        ov[k] = Av * hv[k] + Bv;
    }
    *(float4*)(out + ho) = o;
}

extern "C" void kernel_launch(void* const* d_in, const int* in_sizes, int n_in,
                              void* d_out, int out_size) {
    const float* lr_x = (const float*)d_in[0];
    const float* lr_y = (const float*)d_in[1];
    const float* hr_x = (const float*)d_in[2];
    const float* l_a  = (const float*)d_in[3];
    float* out = (float*)d_out;

    cudaFuncSetAttribute(k_fused, cudaFuncAttributeMaxDynamicSharedMemorySize,
                         SMEM_BYTES);

    k_reduce1<<<96, 256>>>(l_a);
    k_fused<<<PLANES * 64, 512, SMEM_BYTES>>>(lr_x, lr_y, l_a);
    dim3 g(1, HH, PLANES);
    k_up<<<g, 256>>>(hr_x, out);
}

// round 4
// speedup vs baseline: 1.2839x; 1.2611x over previous
#include <cuda_runtime.h>

constexpr int H = 256, W = 256, PLANES = 12;
constexpr int HH = 1024, WH = 1024;
constexpr float EPSF  = 1e-8f;
constexpr float EPSSF = 1e-12f;
constexpr int PSZ = PLANES * H * W;
constexpr int PITCH = 257;

__device__ float g_partial[768];
__device__ float g_hsum[6 * PSZ];
__device__ float g_ab  [2 * PSZ];
__device__ float g_hab [2 * PSZ];
__device__ float g_mab [2 * PSZ];

// ---------- K1: partial sums of |l_a|+eps (float4, 768 blocks) ----------
__global__ void k_reduce1(const float* __restrict__ la) {
    __shared__ float sm[256];
    int t = threadIdx.x;
    float4 v = ((const float4*)la)[blockIdx.x * 256 + t];
    float s = fabsf(v.x) + fabsf(v.y) + fabsf(v.z) + fabsf(v.w) + 4.0f * EPSSF;
    sm[t] = s; __syncthreads();
    for (int off = 128; off > 0; off >>= 1) {
        if (t < off) sm[t] += sm[t + off];
        __syncthreads();
    }
    if (t == 0) g_partial[blockIdx.x] = sm[0];
}

// ---------- K2: products + horizontal 17-tap box ----------
// block = 4 rows of a plane (grid 768). thread slides over 4 cols.
__global__ __launch_bounds__(256)
void k_hbox(const float* __restrict__ lx,
            const float* __restrict__ ly,
            const float* __restrict__ la) {
    __shared__ float sp[6][4][PITCH];
    int t = threadIdx.x;
    int plane = blockIdx.x >> 6, rg = blockIdx.x & 63;
    int row0 = rg * 4;
    int pbase = plane * H * W;

#pragma unroll
    for (int r = 0; r < 4; r++) {
        int idx = pbase + (row0 + r) * W + t;
        float a = fabsf(la[idx]) + EPSSF;
        float x = lx[idx], y = ly[idx];
        float ax = a * x;
        sp[0][r][t] = a;
        sp[1][r][t] = ax * a * y;
        sp[2][r][t] = ax * a;
        sp[3][r][t] = a * y;
        sp[4][r][t] = ax * ax;
        sp[5][r][t] = ax;
    }
    __syncthreads();

    int r = t >> 6, seg = t & 63;
    int c0 = seg * 4;
    float s[6] = {0,0,0,0,0,0};
    int lo = max(0, c0 - 8), hi = min(W - 1, c0 + 8);
    for (int k = lo; k <= hi; k++) {
#pragma unroll
        for (int c = 0; c < 6; c++) s[c] += sp[c][r][k];
    }
    float4 v[6];
#pragma unroll
    for (int c = 0; c < 6; c++) ((float*)&v[c])[0] = s[c];
#pragma unroll
    for (int i = 1; i < 4; i++) {
        int cc = c0 + i;
        int add = cc + 8, sub = cc - 9;
        if (add <= W - 1) {
#pragma unroll
            for (int c = 0; c < 6; c++) s[c] += sp[c][r][add];
        }
        if (sub >= 0) {
#pragma unroll
            for (int c = 0; c < 6; c++) s[c] -= sp[c][r][sub];
        }
#pragma unroll
        for (int c = 0; c < 6; c++) ((float*)&v[c])[i] = s[c];
    }
    int rowbase = pbase + (row0 + r) * W;
#pragma unroll
    for (int c = 0; c < 6; c++)
        ((float4*)(g_hsum + c * PSZ + rowbase))[seg] = v[c];
}

// ---------- K3: vertical 17-tap box + A,b (tile in shared) ----------
// tile: 64 cols x 16 out rows; shared holds 33 rows x 64 cols x 6 ch.
constexpr int K3_FL = 6 * 33 * 64;   // 12672 floats
__global__ __launch_bounds__(256)
void k_vbox_ab() {
    extern __shared__ float hs[];                 // [6][33][64]
    __shared__ float s_inv;
    __shared__ float sred[256];
    int t = threadIdx.x;

    // invS from 768 partials
    float ps = g_partial[t] + g_partial[t + 256] + g_partial[t + 512];
    sred[t] = ps; __syncthreads();
    for (int off = 128; off > 0; off >>= 1) {
        if (t < off) sred[t] += sred[t + off];
        __syncthreads();
    }
    if (t == 0) s_inv = 1.0f / sred[0];

    int plane = blockIdx.x >> 6, tile = blockIdx.x & 63;
    int col0 = (tile & 3) * 64;
    int row0 = (tile >> 2) * 16;
    int pbase = plane * H * W;

    for (int i = t; i < K3_FL; i += 256) {
        int c  = i / (33 * 64);
        int rm = i - c * (33 * 64);
        int r  = rm >> 6, col = rm & 63;
        int gr = row0 - 8 + r;
        hs[i] = (gr >= 0 && gr < H)
              ? g_hsum[c * PSZ + pbase + gr * W + col0 + col] : 0.f;
    }
    __syncthreads();
    float invS = s_inv;

    int col = t & 63, seg = t >> 6;        // 4 out rows per thread
    int lseg = seg * 4;
    float s[6] = {0,0,0,0,0,0};
    for (int r = lseg; r <= lseg + 16; r++) {
#pragma unroll
        for (int c = 0; c < 6; c++) s[c] += hs[(c * 33 + r) * 64 + col];
    }
    int oc = col0 + col;
    int nx = min(W - 1, oc + 8) - max(0, oc - 8) + 1;

#pragma unroll
    for (int i = 0; i < 4; i++) {
        if (i > 0) {
            int po = lseg + i - 1;
#pragma unroll
            for (int c = 0; c < 6; c++)
                s[c] += hs[(c * 33 + po + 17) * 64 + col]
                      - hs[(c * 33 + po) * 64 + col];
        }
        int orow = row0 + lseg + i;
        int ny = min(H - 1, orow + 8) - max(0, orow - 8) + 1;
        float Nf = (float)(nx * ny);
        float invN = 1.0f / Nf;

        float m_a    = s[0] * invN;
        float m_a2xy = s[1] * invN;
        float m_tax  = invS * s[2] * invN;
        float m_ay   = s[3] * invN;
        float m_a2x2 = s[4] * invN;
        float m_ax   = s[5] * invN;

        float temp = fabsf(m_a2x2 - Nf * m_tax * m_ax);
        float A = (m_a2xy - Nf * m_tax * m_ay) / (temp + EPSF);
        float b = (m_ay - A * m_ax) / m_a;

        int o = pbase + orow * W + oc;
        g_ab[o]       = A;
        g_ab[PSZ + o] = b;
    }
}

// ---------- K4: horizontal box of A,b ----------
__global__ __launch_bounds__(256)
void k_hbox2() {
    __shared__ float sp[2][4][PITCH];
    int t = threadIdx.x;
    int plane = blockIdx.x >> 6, rg = blockIdx.x & 63;
    int row0 = rg * 4;
    int pbase = plane * H * W;

#pragma unroll
    for (int r = 0; r < 4; r++) {
        int idx = pbase + (row0 + r) * W + t;
        sp[0][r][t] = g_ab[idx];
        sp[1][r][t] = g_ab[PSZ + idx];
    }
    __syncthreads();

    int r = t >> 6, seg = t & 63;
    int c0 = seg * 4;
    float sa = 0.f, sb = 0.f;
    int lo = max(0, c0 - 8), hi = min(W - 1, c0 + 8);
    for (int k = lo; k <= hi; k++) { sa += sp[0][r][k]; sb += sp[1][r][k]; }
    float4 va, vb;
    ((float*)&va)[0] = sa; ((float*)&vb)[0] = sb;
#pragma unroll
    for (int i = 1; i < 4; i++) {
        int cc = c0 + i;
        int add = cc + 8, sub = cc - 9;
        if (add <= W - 1) { sa += sp[0][r][add]; sb += sp[1][r][add]; }
        if (sub >= 0)     { sa -= sp[0][r][sub]; sb -= sp[1][r][sub]; }
        ((float*)&va)[i] = sa; ((float*)&vb)[i] = sb;
    }
    int rowbase = pbase + (row0 + r) * W;
    ((float4*)(g_hab + rowbase))[seg]       = va;
    ((float4*)(g_hab + PSZ + rowbase))[seg] = vb;
}

// ---------- K5: vertical box of A,b -> means ----------
constexpr int K5_FL = 2 * 33 * 64;
__global__ __launch_bounds__(256)
void k_vbox2() {
    __shared__ float hs[K5_FL];                   // [2][33][64]
    int t = threadIdx.x;
    int plane = blockIdx.x >> 6, tile = blockIdx.x & 63;
    int col0 = (tile & 3) * 64;
    int row0 = (tile >> 2) * 16;
    int pbase = plane * H * W;

    for (int i = t; i < K5_FL; i += 256) {
        int c  = i / (33 * 64);
        int rm = i - c * (33 * 64);
        int r  = rm >> 6, col = rm & 63;
        int gr = row0 - 8 + r;
        hs[i] = (gr >= 0 && gr < H)
              ? g_hab[c * PSZ + pbase + gr * W + col0 + col] : 0.f;
    }
    __syncthreads();

    int col = t & 63, seg = t >> 6;
    int lseg = seg * 4;
    float sa = 0.f, sb = 0.f;
    for (int r = lseg; r <= lseg + 16; r++) {
        sa += hs[(0 * 33 + r) * 64 + col];
        sb += hs[(1 * 33 + r) * 64 + col];
    }
    int oc = col0 + col;
    int nx = min(W - 1, oc + 8) - max(0, oc - 8) + 1;

#pragma unroll
    for (int i = 0; i < 4; i++) {
        if (i > 0) {
            int po = lseg + i - 1;
            sa += hs[(0 * 33 + po + 17) * 64 + col] - hs[(0 * 33 + po) * 64 + col];
            sb += hs[(1 * 33 + po + 17) * 64 + col] - hs[(1 * 33 + po) * 64 + col];
        }
        int orow = row0 + lseg + i;
        int ny = min(H - 1, orow + 8) - max(0, orow - 8) + 1;
        float invN = 1.0f / (float)(nx * ny);
        int o = pbase + orow * W + oc;
        g_mab[o]       = sa * invN;
        g_mab[PSZ + o] = sb * invN;
    }
}

// ---------- K6: bilinear 4x upsample fused with hr_x ----------
// block = 4 output rows of one plane, 512 threads, 8 px/thread (2x float4).
__global__ __launch_bounds__(512)
void k_up(const float* __restrict__ hr, float* __restrict__ out) {
    __shared__ float sA[4 * 256], sB[4 * 256];
    int t = threadIdx.x;
    int plane = blockIdx.x >> 8;
    int g = blockIdx.x & 255;
    int Y0 = g * 4;
    int pb = plane * H * W;
    const float sc = 255.0f / 1023.0f;

#pragma unroll
    for (int jj = 0; jj < 2; jj++) {
        int j = t + jj * 512;
        int r = j >> 8, col = j & 255;
        float yf = (Y0 + r) * sc;
        int y0 = (int)yf;
        int y1 = min(y0 + 1, H - 1);
        float wy = yf - (float)y0;
        float a0 = g_mab[pb + y0 * W + col], a1 = g_mab[pb + y1 * W + col];
        float b0 = g_mab[PSZ + pb + y0 * W + col], b1 = g_mab[PSZ + pb + y1 * W + col];
        sA[j] = a0 + (a1 - a0) * wy;
        sB[j] = b0 + (b1 - b0) * wy;
    }
    __syncthreads();

    int obase = plane * HH * WH + Y0 * WH;
#pragma unroll
    for (int jj = 0; jj < 2; jj++) {
        int i = t + jj * 512;            // float4 index in 4x1024 tile
        int r = i >> 8, x4 = i & 255;
        int ho = obase + r * WH + x4 * 4;
        float4 h = *(const float4*)(hr + ho);
        float4 o;
        float* hv = (float*)&h;
        float* ov = (float*)&o;
#pragma unroll
        for (int k = 0; k < 4; k++) {
            float xf = (x4 * 4 + k) * sc;
            int x0 = (int)xf;
            int x1 = min(x0 + 1, W - 1);
            float wx = xf - (float)x0;
            float Av = sA[r * 256 + x0];
            float Bv = sB[r * 256 + x0];
            Av += (sA[r * 256 + x1] - Av) * wx;
            Bv += (sB[r * 256 + x1] - Bv) * wx;
            ov[k] = Av * hv[k] + Bv;
        }
        *(float4*)(out + ho) = o;
    }
}

extern "C" void kernel_launch(void* const* d_in, const int* in_sizes, int n_in,
                              void* d_out, int out_size) {
    const float* lr_x = (const float*)d_in[0];
    const float* lr_y = (const float*)d_in[1];
    const float* hr_x = (const float*)d_in[2];
    const float* l_a  = (const float*)d_in[3];
    float* out = (float*)d_out;

    static const int K3_SMEM = K3_FL * 4;   // 50688 B
    cudaFuncSetAttribute(k_vbox_ab, cudaFuncAttributeMaxDynamicSharedMemorySize,
                         K3_SMEM);

    k_reduce1<<<768, 256>>>(l_a);
    k_hbox<<<PLANES * 64, 256>>>(lr_x, lr_y, l_a);
    k_vbox_ab<<<PLANES * 64, 256, K3_SMEM>>>();
    k_hbox2<<<PLANES * 64, 256>>>();
    k_vbox2<<<PLANES * 64, 256>>>();
    k_up<<<PLANES * 256, 512>>>(hr_x, out);
}

// round 5
// speedup vs baseline: 1.7376x; 1.3534x over previous
#include <cuda_runtime.h>

constexpr int H = 256, W = 256, PLANES = 12;
constexpr int HH = 1024, WH = 1024;
constexpr float EPSF  = 1e-8f;
constexpr float EPSSF = 1e-12f;
constexpr int PSZ = PLANES * H * W;

constexpr int PRP = 49;   // halo pitch (48 + 1)
constexpr int HSP = 33;   // hsum pitch (32 + 1)

__device__ float  g_partial[768];
__device__ float2 g_ab [PSZ];    // interleaved (A, b)
__device__ float2 g_mab[PSZ];    // interleaved (meanA, meanb)

// ---------- K1: partial sums of |l_a|+eps ----------
__global__ void k_reduce1(const float* __restrict__ la) {
    __shared__ float sm[256];
    int t = threadIdx.x;
    float4 v = ((const float4*)la)[blockIdx.x * 256 + t];
    float s = fabsf(v.x) + fabsf(v.y) + fabsf(v.z) + fabsf(v.w) + 4.0f * EPSSF;
    sm[t] = s; __syncthreads();
    for (int off = 128; off > 0; off >>= 1) {
        if (t < off) sm[t] += sm[t + off];
        __syncthreads();
    }
    if (t == 0) g_partial[blockIdx.x] = sm[0];
}

// ---------- K2: products + H-box + V-box + A,b (one 32x32 tile/block) ----------
constexpr int B1_PROD = 6 * 48 * PRP;          // 14112 floats
constexpr int B1_FL   = B1_PROD + 6 * 48 * HSP;// + 9504 = 23616 floats (94464 B)

__global__ __launch_bounds__(256)
void k_box1(const float* __restrict__ lx,
            const float* __restrict__ ly,
            const float* __restrict__ la) {
    extern __shared__ float smd[];
    float* prod = smd;                  // [6][48][PRP]
    float* hs   = smd + B1_PROD;        // [6][48][HSP]
    __shared__ float sred[256];
    __shared__ float s_inv;

    int t = threadIdx.x;

    // invS
    sred[t] = g_partial[t] + g_partial[t + 256] + g_partial[t + 512];
    __syncthreads();
    for (int off = 128; off > 0; off >>= 1) {
        if (t < off) sred[t] += sred[t + off];
        __syncthreads();
    }
    if (t == 0) s_inv = 1.0f / sred[0];

    int plane = blockIdx.x >> 6, tile = blockIdx.x & 63;
    int R0 = (tile >> 3) * 32;
    int C0 = (tile & 7) * 32;
    int pbase = plane * H * W;

    // phase 1: load 48x48 halo, form products (zero outside image)
    for (int i = t; i < 48 * 48; i += 256) {
        int lr = i / 48, lc = i - lr * 48;
        int gr = R0 - 8 + lr, gc = C0 - 8 + lc;
        float a = 0.f, x = 0.f, y = 0.f;
        if (gr >= 0 && gr < H && gc >= 0 && gc < W) {
            int idx = pbase + gr * W + gc;
            a = fabsf(la[idx]) + EPSSF;
            x = lx[idx];
            y = ly[idx];
        }
        float ax = a * x;
        int o = lr * PRP + lc;
        prod[0 * 48 * PRP + o] = a;
        prod[1 * 48 * PRP + o] = ax * a * y;
        prod[2 * 48 * PRP + o] = ax * a;
        prod[3 * 48 * PRP + o] = a * y;
        prod[4 * 48 * PRP + o] = ax * ax;
        prod[5 * 48 * PRP + o] = ax;
    }
    __syncthreads();

    // phase 2: horizontal 17-tap box, sliding over 4-col segments.
    // 48 rows x 8 segs = 384 jobs.
    for (int j = t; j < 384; j += 256) {
        int r = j >> 3, sgc = j & 7;
        int lc0 = sgc * 4;
        float s[6] = {0,0,0,0,0,0};
#pragma unroll
        for (int k = 0; k < 17; k++) {
#pragma unroll
            for (int c = 0; c < 6; c++)
                s[c] += prod[(c * 48 + r) * PRP + lc0 + k];
        }
#pragma unroll
        for (int c = 0; c < 6; c++) hs[(c * 48 + r) * HSP + lc0] = s[c];
#pragma unroll
        for (int i = 1; i < 4; i++) {
#pragma unroll
            for (int c = 0; c < 6; c++) {
                s[c] += prod[(c * 48 + r) * PRP + lc0 + 16 + i]
                      - prod[(c * 48 + r) * PRP + lc0 + i - 1];
                hs[(c * 48 + r) * HSP + lc0 + i] = s[c];
            }
        }
    }
    __syncthreads();
    float invS = s_inv;

    // phase 3: vertical 17-tap box + A,b. 32 cols x 8 segs = 256 jobs.
    int col = t & 31, seg = t >> 5;
    int rl0 = seg * 4;
    float s[6] = {0,0,0,0,0,0};
#pragma unroll
    for (int k = 0; k < 17; k++) {
#pragma unroll
        for (int c = 0; c < 6; c++)
            s[c] += hs[(c * 48 + rl0 + k) * HSP + col];
    }
    int oc = C0 + col;
    int nx = min(W - 1, oc + 8) - max(0, oc - 8) + 1;

#pragma unroll
    for (int i = 0; i < 4; i++) {
        if (i > 0) {
#pragma unroll
            for (int c = 0; c < 6; c++)
                s[c] += hs[(c * 48 + rl0 + 16 + i) * HSP + col]
                      - hs[(c * 48 + rl0 + i - 1) * HSP + col];
        }
        int orow = R0 + rl0 + i;
        int ny = min(H - 1, orow + 8) - max(0, orow - 8) + 1;
        float Nf = (float)(nx * ny);
        float invN = 1.0f / Nf;

        float m_a    = s[0] * invN;
        float m_a2xy = s[1] * invN;
        float m_tax  = invS * s[2] * invN;
        float m_ay   = s[3] * invN;
        float m_a2x2 = s[4] * invN;
        float m_ax   = s[5] * invN;

        float temp = fabsf(m_a2x2 - Nf * m_tax * m_ax);
        float A = (m_a2xy - Nf * m_tax * m_ay) / (temp + EPSF);
        float b = (m_ay - A * m_ax) / m_a;

        g_ab[pbase + orow * W + oc] = make_float2(A, b);
    }
}

// ---------- K3: H-box + V-box of A,b -> means (one 32x32 tile/block) ----------
__global__ __launch_bounds__(256)
void k_box2() {
    __shared__ float ab [2 * 48 * PRP];   // 4704 fl
    __shared__ float hs2[2 * 48 * HSP];   // 3168 fl
    int t = threadIdx.x;
    int plane = blockIdx.x >> 6, tile = blockIdx.x & 63;
    int R0 = (tile >> 3) * 32;
    int C0 = (tile & 7) * 32;
    int pbase = plane * H * W;

    for (int i = t; i < 48 * 48; i += 256) {
        int lr = i / 48, lc = i - lr * 48;
        int gr = R0 - 8 + lr, gc = C0 - 8 + lc;
        float2 v = make_float2(0.f, 0.f);
        if (gr >= 0 && gr < H && gc >= 0 && gc < W)
            v = g_ab[pbase + gr * W + gc];
        ab[(0 * 48 + lr) * PRP + lc] = v.x;
        ab[(1 * 48 + lr) * PRP + lc] = v.y;
    }
    __syncthreads();

    for (int j = t; j < 384; j += 256) {
        int r = j >> 3, sgc = j & 7;
        int lc0 = sgc * 4;
        float sa = 0.f, sb = 0.f;
#pragma unroll
        for (int k = 0; k < 17; k++) {
            sa += ab[(0 * 48 + r) * PRP + lc0 + k];
            sb += ab[(1 * 48 + r) * PRP + lc0 + k];
        }
        hs2[(0 * 48 + r) * HSP + lc0] = sa;
        hs2[(1 * 48 + r) * HSP + lc0] = sb;
#pragma unroll
        for (int i = 1; i < 4; i++) {
            sa += ab[(0 * 48 + r) * PRP + lc0 + 16 + i]
                - ab[(0 * 48 + r) * PRP + lc0 + i - 1];
            sb += ab[(1 * 48 + r) * PRP + lc0 + 16 + i]
                - ab[(1 * 48 + r) * PRP + lc0 + i - 1];
            hs2[(0 * 48 + r) * HSP + lc0 + i] = sa;
            hs2[(1 * 48 + r) * HSP + lc0 + i] = sb;
        }
    }
    __syncthreads();

    int col = t & 31, seg = t >> 5;
    int rl0 = seg * 4;
    float sa = 0.f, sb = 0.f;
#pragma unroll
    for (int k = 0; k < 17; k++) {
        sa += hs2[(0 * 48 + rl0 + k) * HSP + col];
        sb += hs2[(1 * 48 + rl0 + k) * HSP + col];
    }
    int oc = C0 + col;
    int nx = min(W - 1, oc + 8) - max(0, oc - 8) + 1;

#pragma unroll
    for (int i = 0; i < 4; i++) {
        if (i > 0) {
            sa += hs2[(0 * 48 + rl0 + 16 + i) * HSP + col]
                - hs2[(0 * 48 + rl0 + i - 1) * HSP + col];
            sb += hs2[(1 * 48 + rl0 + 16 + i) * HSP + col]
                - hs2[(1 * 48 + rl0 + i - 1) * HSP + col];
        }
        int orow = R0 + rl0 + i;
        int ny = min(H - 1, orow + 8) - max(0, orow - 8) + 1;
        float invN = 1.0f / (float)(nx * ny);
        g_mab[pbase + orow * W + oc] = make_float2(sa * invN, sb * invN);
    }
}

// ---------- K4: bilinear 4x upsample fused with hr_x ----------
__global__ __launch_bounds__(512)
void k_up(const float* __restrict__ hr, float* __restrict__ out) {
    __shared__ float sA[4 * 256], sB[4 * 256];
    int t = threadIdx.x;
    int plane = blockIdx.x >> 8;
    int g = blockIdx.x & 255;
    int Y0 = g * 4;
    int pb = plane * H * W;
    const float sc = 255.0f / 1023.0f;

#pragma unroll
    for (int jj = 0; jj < 2; jj++) {
        int j = t + jj * 512;
        int r = j >> 8, col = j & 255;
        float yf = (Y0 + r) * sc;
        int y0 = (int)yf;
        int y1 = min(y0 + 1, H - 1);
        float wy = yf - (float)y0;
        float2 v0 = g_mab[pb + y0 * W + col];
        float2 v1 = g_mab[pb + y1 * W + col];
        sA[j] = v0.x + (v1.x - v0.x) * wy;
        sB[j] = v0.y + (v1.y - v0.y) * wy;
    }
    __syncthreads();

    int obase = plane * HH * WH + Y0 * WH;
#pragma unroll
    for (int jj = 0; jj < 2; jj++) {
        int i = t + jj * 512;
        int r = i >> 8, x4 = i & 255;
        int ho = obase + r * WH + x4 * 4;
        float4 h = *(const float4*)(hr + ho);
        float4 o;
        float* hv = (float*)&h;
        float* ov = (float*)&o;
#pragma unroll
        for (int k = 0; k < 4; k++) {
            float xf = (x4 * 4 + k) * sc;
            int x0 = (int)xf;
            int x1 = min(x0 + 1, W - 1);
            float wx = xf - (float)x0;
            float Av = sA[r * 256 + x0];
            float Bv = sB[r * 256 + x0];
            Av += (sA[r * 256 + x1] - Av) * wx;
            Bv += (sB[r * 256 + x1] - Bv) * wx;
            ov[k] = Av * hv[k] + Bv;
        }
        *(float4*)(out + ho) = o;
    }
}

extern "C" void kernel_launch(void* const* d_in, const int* in_sizes, int n_in,
                              void* d_out, int out_size) {
    const float* lr_x = (const float*)d_in[0];
    const float* lr_y = (const float*)d_in[1];
    const float* hr_x = (const float*)d_in[2];
    const float* l_a  = (const float*)d_in[3];
    float* out = (float*)d_out;

    static const int B1_SMEM = B1_FL * 4;    // 94464 B
    cudaFuncSetAttribute(k_box1, cudaFuncAttributeMaxDynamicSharedMemorySize,
                         B1_SMEM);

    k_reduce1<<<768, 256>>>(l_a);
    k_box1<<<PLANES * 64, 256, B1_SMEM>>>(lr_x, lr_y, l_a);
    k_box2<<<PLANES * 64, 256>>>();
    k_up<<<PLANES * 256, 512>>>(hr_x, out);
}

// round 6
// speedup vs baseline: 2.0309x; 1.1688x over previous
#include <cuda_runtime.h>

constexpr int H = 256, W = 256, PLANES = 12;
constexpr int HH = 1024, WH = 1024;
constexpr float EPSF  = 1e-8f;
constexpr float EPSSF = 1e-12f;
constexpr int PSZ = PLANES * H * W;

constexpr int PRP = 49;   // halo pitch (48 + 1)
constexpr int HSP = 33;   // hsum pitch (32 + 1)

__device__ float  g_partial[768];
__device__ float2 g_ab [PSZ];    // interleaved (A, b)
__device__ float2 g_mab[PSZ];    // interleaved (meanA, meanb)

// ---------- K1: partial sums of |l_a|+eps ----------
__global__ void k_reduce1(const float* __restrict__ la) {
    __shared__ float sm[256];
    int t = threadIdx.x;
    float4 v = ((const float4*)la)[blockIdx.x * 256 + t];
    float s = fabsf(v.x) + fabsf(v.y) + fabsf(v.z) + fabsf(v.w) + 4.0f * EPSSF;
    sm[t] = s; __syncthreads();
    for (int off = 128; off > 0; off >>= 1) {
        if (t < off) sm[t] += sm[t + off];
        __syncthreads();
    }
    if (t == 0) g_partial[blockIdx.x] = sm[0];
}

// ---------- K2: a,x,y staged; products computed inside the H-box slide ----------
constexpr int B1_AXY = 3 * 48 * PRP;            // 7056 floats
constexpr int B1_FL  = B1_AXY + 6 * 48 * HSP;   // +9504 = 16560 floats (66240 B)

__device__ __forceinline__ void acc_prod(float* s, float a, float x, float y,
                                         float sign) {
    float ax  = a * x;
    float a2x = ax * a;
    s[0] += sign * a;
    s[1] += sign * a2x * y;
    s[2] += sign * a2x;
    s[3] += sign * a * y;
    s[4] += sign * ax * ax;
    s[5] += sign * ax;
}

__global__ __launch_bounds__(256)
void k_box1(const float* __restrict__ lx,
            const float* __restrict__ ly,
            const float* __restrict__ la) {
    extern __shared__ float smd[];
    float* sa = smd;
    float* sx = smd + 48 * PRP;
    float* sy = smd + 2 * 48 * PRP;
    float* hs = smd + B1_AXY;        // [6][48][HSP]
    __shared__ float sred[256];
    __shared__ float s_inv;

    int t = threadIdx.x;

    sred[t] = g_partial[t] + g_partial[t + 256] + g_partial[t + 512];
    __syncthreads();
    for (int off = 128; off > 0; off >>= 1) {
        if (t < off) sred[t] += sred[t + off];
        __syncthreads();
    }
    if (t == 0) s_inv = 1.0f / sred[0];

    int plane = blockIdx.x >> 6, tile = blockIdx.x & 63;
    int R0 = (tile >> 3) * 32;
    int C0 = (tile & 7) * 32;
    int pbase = plane * H * W;

    // phase 1: stage 48x48 halo of a,x,y (zero outside image)
    for (int i = t; i < 48 * 48; i += 256) {
        int lr = i / 48, lc = i - lr * 48;
        int gr = R0 - 8 + lr, gc = C0 - 8 + lc;
        float a = 0.f, x = 0.f, y = 0.f;
        if (gr >= 0 && gr < H && gc >= 0 && gc < W) {
            int idx = pbase + gr * W + gc;
            a = fabsf(la[idx]) + EPSSF;
            x = lx[idx];
            y = ly[idx];
        }
        int o = lr * PRP + lc;
        sa[o] = a; sx[o] = x; sy[o] = y;
    }
    __syncthreads();

    // phase 2: H-box with on-the-fly products. 48 rows x 8 segs = 384 jobs.
    for (int j = t; j < 384; j += 256) {
        int r = j >> 3, sg = j & 7;
        int base = r * PRP + sg * 4;
        float s[6] = {0,0,0,0,0,0};
#pragma unroll
        for (int k = 0; k < 17; k++)
            acc_prod(s, sa[base + k], sx[base + k], sy[base + k], 1.0f);
        int ho = r * HSP + sg * 4;
#pragma unroll
        for (int c = 0; c < 6; c++) hs[c * 48 * HSP + ho] = s[c];
#pragma unroll
        for (int i = 1; i < 4; i++) {
            int add = base + 16 + i, sub = base + i - 1;
            acc_prod(s, sa[add], sx[add], sy[add], 1.0f);
            acc_prod(s, sa[sub], sx[sub], sy[sub], -1.0f);
#pragma unroll
            for (int c = 0; c < 6; c++) hs[c * 48 * HSP + ho + i] = s[c];
        }
    }
    __syncthreads();
    float invS = s_inv;

    // phase 3: V-box + A,b. 32 cols x 8 row-segs = 256 jobs.
    int col = t & 31, seg = t >> 5;
    int rl0 = seg * 4;
    float s[6] = {0,0,0,0,0,0};
#pragma unroll
    for (int k = 0; k < 17; k++) {
#pragma unroll
        for (int c = 0; c < 6; c++)
            s[c] += hs[(c * 48 + rl0 + k) * HSP + col];
    }
    int oc = C0 + col;
    int nx = min(W - 1, oc + 8) - max(0, oc - 8) + 1;

#pragma unroll
    for (int i = 0; i < 4; i++) {
        if (i > 0) {
#pragma unroll
            for (int c = 0; c < 6; c++)
                s[c] += hs[(c * 48 + rl0 + 16 + i) * HSP + col]
                      - hs[(c * 48 + rl0 + i - 1) * HSP + col];
        }
        int orow = R0 + rl0 + i;
        int ny = min(H - 1, orow + 8) - max(0, orow - 8) + 1;
        float Nf = (float)(nx * ny);
        float invN = 1.0f / Nf;

        float m_a    = s[0] * invN;
        float m_a2xy = s[1] * invN;
        float m_tax  = invS * s[2] * invN;
        float m_ay   = s[3] * invN;
        float m_a2x2 = s[4] * invN;
        float m_ax   = s[5] * invN;

        float temp = fabsf(m_a2x2 - Nf * m_tax * m_ax);
        float A = (m_a2xy - Nf * m_tax * m_ay) / (temp + EPSF);
        float b = (m_ay - A * m_ax) / m_a;

        g_ab[pbase + orow * W + oc] = make_float2(A, b);
    }
}

// ---------- K3: H-box + V-box of A,b -> means ----------
__global__ __launch_bounds__(256)
void k_box2() {
    __shared__ float ab [2 * 48 * PRP];
    __shared__ float hs2[2 * 48 * HSP];
    int t = threadIdx.x;
    int plane = blockIdx.x >> 6, tile = blockIdx.x & 63;
    int R0 = (tile >> 3) * 32;
    int C0 = (tile & 7) * 32;
    int pbase = plane * H * W;

    for (int i = t; i < 48 * 48; i += 256) {
        int lr = i / 48, lc = i - lr * 48;
        int gr = R0 - 8 + lr, gc = C0 - 8 + lc;
        float2 v = make_float2(0.f, 0.f);
        if (gr >= 0 && gr < H && gc >= 0 && gc < W)
            v = g_ab[pbase + gr * W + gc];
        ab[(0 * 48 + lr) * PRP + lc] = v.x;
        ab[(1 * 48 + lr) * PRP + lc] = v.y;
    }
    __syncthreads();

    for (int j = t; j < 384; j += 256) {
        int r = j >> 3, sgc = j & 7;
        int lc0 = sgc * 4;
        float sav = 0.f, sbv = 0.f;
#pragma unroll
        for (int k = 0; k < 17; k++) {
            sav += ab[(0 * 48 + r) * PRP + lc0 + k];
            sbv += ab[(1 * 48 + r) * PRP + lc0 + k];
        }
        hs2[(0 * 48 + r) * HSP + lc0] = sav;
        hs2[(1 * 48 + r) * HSP + lc0] = sbv;
#pragma unroll
        for (int i = 1; i < 4; i++) {
            sav += ab[(0 * 48 + r) * PRP + lc0 + 16 + i]
                 - ab[(0 * 48 + r) * PRP + lc0 + i - 1];
            sbv += ab[(1 * 48 + r) * PRP + lc0 + 16 + i]
                 - ab[(1 * 48 + r) * PRP + lc0 + i - 1];
            hs2[(0 * 48 + r) * HSP + lc0 + i] = sav;
            hs2[(1 * 48 + r) * HSP + lc0 + i] = sbv;
        }
    }
    __syncthreads();

    int col = t & 31, seg = t >> 5;
    int rl0 = seg * 4;
    float sav = 0.f, sbv = 0.f;
#pragma unroll
    for (int k = 0; k < 17; k++) {
        sav += hs2[(0 * 48 + rl0 + k) * HSP + col];
        sbv += hs2[(1 * 48 + rl0 + k) * HSP + col];
    }
    int oc = C0 + col;
    int nx = min(W - 1, oc + 8) - max(0, oc - 8) + 1;

#pragma unroll
    for (int i = 0; i < 4; i++) {
        if (i > 0) {
            sav += hs2[(0 * 48 + rl0 + 16 + i) * HSP + col]
                 - hs2[(0 * 48 + rl0 + i - 1) * HSP + col];
            sbv += hs2[(1 * 48 + rl0 + 16 + i) * HSP + col]
                 - hs2[(1 * 48 + rl0 + i - 1) * HSP + col];
        }
        int orow = R0 + rl0 + i;
        int ny = min(H - 1, orow + 8) - max(0, orow - 8) + 1;
        float invN = 1.0f / (float)(nx * ny);
        g_mab[pbase + orow * W + oc] = make_float2(sav * invN, sbv * invN);
    }
}

// ---------- K4: bilinear 4x upsample fused with hr_x ----------
// 4 rows x 1024 per block; per-group-of-4 tap preload, no per-px F2I/min.
__global__ __launch_bounds__(512)
void k_up(const float* __restrict__ hr, float* __restrict__ out) {
    __shared__ float2 sAB[4][258];
    int t = threadIdx.x;
    int plane = blockIdx.x >> 8;
    int g = blockIdx.x & 255;
    int Y0 = g * 4;
    int pb = plane * H * W;
    const float sc = 255.0f / 1023.0f;

#pragma unroll
    for (int jj = 0; jj < 2; jj++) {
        int j = t + jj * 512;
        int r = j >> 8, col = j & 255;
        float yf = (Y0 + r) * sc;
        int y0 = (int)yf;
        int y1 = min(y0 + 1, H - 1);
        float wy = yf - (float)y0;
        float2 v0 = g_mab[pb + y0 * W + col];
        float2 v1 = g_mab[pb + y1 * W + col];
        float2 res = make_float2(v0.x + (v1.x - v0.x) * wy,
                                 v0.y + (v1.y - v0.y) * wy);
        sAB[r][col] = res;
        if (col == 255) sAB[r][256] = res;
    }
    __syncthreads();

    int obase = plane * HH * WH + Y0 * WH;
#pragma unroll
    for (int jj = 0; jj < 2; jj++) {
        int i = t + jj * 512;
        int r = i >> 8, x4 = i & 255;
        int X0 = x4 * 4;
        float xf0 = (float)X0 * sc;
        int x0 = (int)xf0;
        float xv = (float)x0;
        float2 p0 = sAB[r][x0];
        float2 p1 = sAB[r][x0 + 1];
        float2 p2 = sAB[r][x0 + 2];

        int ho = obase + r * WH + X0;
        float4 h = *(const float4*)(hr + ho);
        float4 o;
        float* hv = (float*)&h;
        float* ov = (float*)&o;
#pragma unroll
        for (int k = 0; k < 4; k++) {
            float xf = (float)(X0 + k) * sc;
            float d = xf - xv;
            bool st = d >= 1.0f;
            float wx = st ? d - 1.0f : d;
            float alo = st ? p1.x : p0.x;
            float ahi = st ? p2.x : p1.x;
            float blo = st ? p1.y : p0.y;
            float bhi = st ? p2.y : p1.y;
            float Av = alo + (ahi - alo) * wx;
            float Bv = blo + (bhi - blo) * wx;
            ov[k] = fmaf(Av, hv[k], Bv);
        }
        *(float4*)(out + ho) = o;
    }
}

extern "C" void kernel_launch(void* const* d_in, const int* in_sizes, int n_in,
                              void* d_out, int out_size) {
    const float* lr_x = (const float*)d_in[0];
    const float* lr_y = (const float*)d_in[1];
    const float* hr_x = (const float*)d_in[2];
    const float* l_a  = (const float*)d_in[3];
    float* out = (float*)d_out;

    static const int B1_SMEM = B1_FL * 4;    // 66240 B
    cudaFuncSetAttribute(k_box1, cudaFuncAttributeMaxDynamicSharedMemorySize,
                         B1_SMEM);

    k_reduce1<<<768, 256>>>(l_a);
    k_box1<<<PLANES * 64, 256, B1_SMEM>>>(lr_x, lr_y, l_a);
    k_box2<<<PLANES * 64, 256>>>();
    k_up<<<PLANES * 256, 512>>>(hr_x, out);
}